// round 3
// baseline (speedup 1.0000x reference)
#include <cuda_runtime.h>
#include <math.h>

#define NPTS 16384
#define DIM  64
#define NC   9
#define TILE 64
#define NF4  16      // float4s per row of data
#define PITCHF4 17   // padded row pitch in float4 units

// ---- device scratch ----
__device__ float g_fn[NPTS * DIM];     // normalized features (valid points only)
__device__ int   g_cls[NPTS];          // class 1..8 if valid member, else 0
__device__ int   g_cidx[NPTS];         // class-sorted point indices
__device__ int   g_ccls[NPTS];         // class-sorted classes (ascending)
__device__ int   g_nvalid;
__device__ int   g_cnt[NC];
__device__ float g_sum[NC * DIM];      // per-class normalized-feature sums
__device__ float g_cross[NC * NC];     // relu(dot) sums per unordered class pair
__device__ unsigned g_ticket;

// ---------------- K0: zero accumulators ----------------
__global__ void k0_zero() {
    int t = threadIdx.x;
    if (t < NC) g_cnt[t] = 0;
    if (t < NC * NC) g_cross[t] = 0.f;
    for (int i = t; i < NC * DIM; i += blockDim.x) g_sum[i] = 0.f;
    if (t == 0) { g_nvalid = 0; g_ticket = 0; }
}

// ---------------- K1: classify + normalize (1 warp / point) ----------------
__global__ void k1_classify(const int* __restrict__ labels,
                            const float* __restrict__ feats,
                            const float* __restrict__ scores) {
    int warp = (blockIdx.x * blockDim.x + threadIdx.x) >> 5;
    int lane = threadIdx.x & 31;
    if (warp >= NPTS) return;
    int p = warp;

    float x0 = feats[p * DIM + lane];
    float x1 = feats[p * DIM + 32 + lane];
    float ss = x0 * x0 + x1 * x1;
    #pragma unroll
    for (int o = 16; o > 0; o >>= 1) ss += __shfl_xor_sync(0xffffffffu, ss, o);
    float inv = 1.0f / fmaxf(sqrtf(ss), 1e-12f);

    // softmax argmax + max prob (9 classes on first 9 lanes)
    float s = (lane < NC) ? scores[p * NC + lane] : -INFINITY;
    float mval = s; int midx = lane;
    #pragma unroll
    for (int o = 16; o > 0; o >>= 1) {
        float ov = __shfl_xor_sync(0xffffffffu, mval, o);
        int   oi = __shfl_xor_sync(0xffffffffu, midx, o);
        if (ov > mval || (ov == mval && oi < midx)) { mval = ov; midx = oi; }
    }
    float e = (lane < NC) ? expf(s - mval) : 0.f;
    #pragma unroll
    for (int o = 16; o > 0; o >>= 1) e += __shfl_xor_sync(0xffffffffu, e, o);
    float pmax = 1.0f / e;

    int lab = labels[p];
    int valid = (lab == midx) && (pmax >= 0.5f);
    int cls = (valid && lab >= 1) ? lab : 0;

    if (lane == 0) g_cls[p] = cls;
    if (cls > 0) {
        float f0 = x0 * inv, f1 = x1 * inv;
        g_fn[p * DIM + lane]      = f0;
        g_fn[p * DIM + 32 + lane] = f1;
        atomicAdd(&g_sum[cls * DIM + lane],      f0);
        atomicAdd(&g_sum[cls * DIM + 32 + lane], f1);
        if (lane == 0) atomicAdd(&g_cnt[cls], 1);
    }
}

// ---------------- K2: class-stable counting sort (single block, 1024 thr) ----
__global__ void k2_sort() {
    __shared__ int cstart[NC];
    __shared__ int running[NC];
    __shared__ int wcnt[NC][32];
    __shared__ int woff[NC][32];
    __shared__ int wtot[NC];
    int tid = threadIdx.x, lane = tid & 31, wid = tid >> 5;

    if (tid == 0) {
        int acc = 0;
        for (int c = 1; c < NC; c++) { cstart[c] = acc; acc += g_cnt[c]; }
        g_nvalid = acc;
    }
    if (tid < NC) running[tid] = 0;
    __syncthreads();

    unsigned lmask = (1u << lane) - 1u;
    for (int start = 0; start < NPTS; start += 1024) {
        int p = start + tid;
        int c = g_cls[p];
        int my_pre = 0;
        #pragma unroll
        for (int cc = 1; cc < NC; cc++) {
            unsigned bal = __ballot_sync(0xffffffffu, c == cc);
            if (c == cc) my_pre = __popc(bal & lmask);
            if (lane == 0) wcnt[cc][wid] = __popc(bal);
        }
        __syncthreads();
        if (wid < NC - 1) {
            int cc = wid + 1;
            int v = wcnt[cc][lane];
            int inc = v;
            #pragma unroll
            for (int o = 1; o < 32; o <<= 1) {
                int t2 = __shfl_up_sync(0xffffffffu, inc, o);
                if (lane >= o) inc += t2;
            }
            woff[cc][lane] = inc - v;
            if (lane == 31) wtot[cc] = inc;
        }
        __syncthreads();
        if (c > 0) {
            int pos = cstart[c] + running[c] + woff[c][wid] + my_pre;
            g_cidx[pos] = p;
            g_ccls[pos] = c;
        }
        __syncthreads();
        if (tid >= 1 && tid < NC) running[tid] += wtot[tid];
        __syncthreads();
    }
}

// ---------------- K3: pairwise relu(dot), 4x4 register blocking ------------
// Tiles stored as float4 with row-rotate swizzle: logical float4 column c of
// row r lives at physical column (c + r) & 15. All accesses 16B-aligned.
__device__ __forceinline__ void dot4x4(const float4 (*As)[PITCHF4],
                                       const float4 (*Bs)[PITCHF4],
                                       int i0, int j0, float* acc) {
    #pragma unroll
    for (int r = 0; r < 16; r++) acc[r] = 0.f;
    #pragma unroll 4
    for (int dd = 0; dd < NF4; dd++) {
        float4 a[4], b[4];
        #pragma unroll
        for (int r = 0; r < 4; r++) a[r] = As[i0 + r][(dd + i0 + r) & 15];
        #pragma unroll
        for (int s = 0; s < 4; s++) b[s] = Bs[j0 + s][(dd + j0 + s) & 15];
        #pragma unroll
        for (int r = 0; r < 4; r++)
            #pragma unroll
            for (int s = 0; s < 4; s++)
                acc[r * 4 + s] += a[r].x * b[s].x + a[r].y * b[s].y
                                + a[r].z * b[s].z + a[r].w * b[s].w;
    }
}

__global__ void __launch_bounds__(256, 2) k3_pairs(float* __restrict__ out) {
    __shared__ float4 As[TILE][PITCHF4];
    __shared__ float4 Bs[TILE][PITCHF4];
    __shared__ int    acl[TILE], bcl[TILE];
    __shared__ float  scross[NC * NC];

    int tid = threadIdx.x;
    int tx = tid & 15, ty = tid >> 4;
    for (int i = tid; i < NC * NC; i += 256) scross[i] = 0.f;

    int nv = g_nvalid;
    int nt = (nv + TILE - 1) / TILE;
    int ntp = nt * (nt + 1) / 2;

    const float4 z4 = make_float4(0.f, 0.f, 0.f, 0.f);

    for (int k = blockIdx.x; k < ntp; k += gridDim.x) {
        int tj = (int)((sqrtf(8.0f * (float)k + 1.0f) - 1.0f) * 0.5f);
        while ((tj + 1) * (tj + 2) / 2 <= k) tj++;
        while (tj * (tj + 1) / 2 > k) tj--;
        int ti = k - tj * (tj + 1) / 2;

        __syncthreads();
        for (int q = tid; q < TILE * NF4; q += 256) {
            int row = q >> 4, c4 = q & 15;
            int pc = (c4 + row) & 15;  // swizzled physical column
            int va = ti * TILE + row, vb = tj * TILE + row;
            float4 a = z4, b = z4;
            if (va < nv) a = *(const float4*)&g_fn[g_cidx[va] * DIM + c4 * 4];
            if (vb < nv) b = *(const float4*)&g_fn[g_cidx[vb] * DIM + c4 * 4];
            As[row][pc] = a;
            Bs[row][pc] = b;
        }
        if (tid < TILE) {
            int va = ti * TILE + tid, vb = tj * TILE + tid;
            acl[tid] = (va < nv) ? g_ccls[va] : 0;
            bcl[tid] = (vb < nv) ? g_ccls[vb] : 0;
        }
        __syncthreads();

        int i0 = ty * 4, j0 = tx * 4;
        int ca = acl[i0], cb = bcl[j0];
        bool ua = (acl[i0+1] == ca) & (acl[i0+2] == ca) & (acl[i0+3] == ca);
        bool ub = (bcl[j0+1] == cb) & (bcl[j0+2] == cb) & (bcl[j0+3] == cb);
        bool diag = (ti == tj);

        if (ua && ub) {
            // uniform 4x4 class block (vast majority with class-sorted data)
            if (ca == cb) continue;                 // same class or both pad
            if (ca == 0 || cb == 0) continue;       // padding
            if (diag && ca > cb) continue;          // dedup mirror on diagonal
            float acc[16];
            dot4x4(As, Bs, i0, j0, acc);
            float s = 0.f;
            #pragma unroll
            for (int r = 0; r < 16; r++) s += fmaxf(acc[r], 0.f);
            int lo = min(ca, cb), hi = max(ca, cb);
            if (s > 0.f) atomicAdd(&scross[lo * NC + hi], s);
        } else {
            // class-boundary block: per-element path
            float acc[16];
            dot4x4(As, Bs, i0, j0, acc);
            #pragma unroll
            for (int r = 0; r < 4; r++) {
                #pragma unroll
                for (int sI = 0; sI < 4; sI++) {
                    int ci = acl[i0 + r], cj = bcl[j0 + sI];
                    if (ci == 0 || cj == 0 || ci == cj) continue;
                    if (diag && (i0 + r) >= (j0 + sI)) continue;
                    float v = acc[r * 4 + sI];
                    if (v > 0.f) {
                        int lo = min(ci, cj), hi = max(ci, cj);
                        atomicAdd(&scross[lo * NC + hi], v);
                    }
                }
            }
        }
    }
    __syncthreads();
    for (int i = tid; i < NC * NC; i += 256)
        if (scross[i] != 0.f) atomicAdd(&g_cross[i], scross[i]);

    // ---- last-block finalize (fused k4) ----
    __shared__ bool is_last;
    __threadfence();
    __syncthreads();
    if (tid == 0) is_last = (atomicAdd(&g_ticket, 1u) == gridDim.x - 1);
    __syncthreads();
    if (!is_last) return;
    __threadfence();

    __shared__ float red[256];
    float acc = 0.f;
    if (tid >= 1 && tid < NC) {
        float cnt = (float)g_cnt[tid];
        float quad = 0.f;
        #pragma unroll
        for (int d = 0; d < DIM; d++) {
            float v = g_sum[tid * DIM + d];
            quad += v * v;
        }
        float npairs = cnt * (cnt - 1.0f) * 0.5f;
        if (npairs > 0.f)
            acc += 1.0f - ((quad - cnt) * 0.5f) / npairs;
    }
    for (int idx = tid; idx < NC * NC; idx += 256) {
        int a = idx / NC, b = idx % NC;
        if (a >= 1 && b > a) {
            float den = (float)g_cnt[a] * (float)g_cnt[b];
            if (den > 0.f) acc += g_cross[a * NC + b] / den;
        }
    }
    red[tid] = acc;
    __syncthreads();
    #pragma unroll
    for (int o = 128; o > 0; o >>= 1) {
        if (tid < o) red[tid] += red[tid + o];
        __syncthreads();
    }
    if (tid == 0) out[0] = red[0];
}

extern "C" void kernel_launch(void* const* d_in, const int* in_sizes, int n_in,
                              void* d_out, int out_size) {
    const int*   labels = nullptr;
    const float* feats  = nullptr;
    const float* scores = nullptr;
    for (int i = 0; i < n_in; i++) {
        if (in_sizes[i] == NPTS)            labels = (const int*)d_in[i];
        else if (in_sizes[i] == NPTS * DIM) feats  = (const float*)d_in[i];
        else if (in_sizes[i] == NPTS * NC)  scores = (const float*)d_in[i];
    }
    float* out = (float*)d_out;

    k0_zero<<<1, 256>>>();
    k1_classify<<<(NPTS * 32) / 256, 256>>>(labels, feats, scores);
    k2_sort<<<1, 1024>>>();
    k3_pairs<<<148, 256>>>(out);
}